// round 4
// baseline (speedup 1.0000x reference)
#include <cuda_runtime.h>
#include <math.h>

// VanillaVQ: z_e (8,64,64,64) fp32, embedding (8192,64) fp32.
// Outputs (concat fp32): z_q (2097152) | indices (32768) | commit_loss | perplexity | usage.

#define K_CODES 8192
#define D_DIM   64
#define N_ROWS  32768      // 8*64*64
#define HW      4096       // 64*64
#define TK      128        // codes per smem tile
#define THREADS 128
#define RPT     2          // rows per thread
#define BETA    0.25f

#define NZ (N_ROWS * D_DIM)
#define NI N_ROWS

typedef unsigned long long ull;

// Scratch (no cudaMalloc allowed)
__device__ float g_b2[K_CODES];      // |e_k|^2, XLA warp-tree order
__device__ int   g_counts[K_CODES];
__device__ float g_loss;

// packed helpers — each lane is an independent IEEE fp32 op (bitwise == scalar)
__device__ __forceinline__ ull pack2(float lo, float hi) {
    ull r; asm("mov.b64 %0, {%1,%2};" : "=l"(r) : "f"(lo), "f"(hi)); return r;
}
__device__ __forceinline__ void unpack2(float& lo, float& hi, ull v) {
    asm("mov.b64 {%0,%1}, %2;" : "=f"(lo), "=f"(hi) : "l"(v));
}
#define FMA2(acc, a, b) asm("fma.rn.f32x2 %0, %1, %2, %0;" : "+l"(acc) : "l"(a), "l"(b))
__device__ __forceinline__ ull fma2v(ull a, ull b, ull c) {
    ull r; asm("fma.rn.f32x2 %0, %1, %2, %3;" : "=l"(r) : "l"(a), "l"(b), "l"(c)); return r;
}
__device__ __forceinline__ ull add2v(ull a, ull b) {
    ull r; asm("add.rn.f32x2 %0, %1, %2;" : "=l"(r) : "l"(a), "l"(b)); return r;
}

// ---------------------------------------------------------------------------
// Kernel 1: per-code squared norm in XLA warp-tree order (one warp per code)
// ---------------------------------------------------------------------------
__global__ void vq_prep(const float* __restrict__ emb) {
    int gtid = blockIdx.x * blockDim.x + threadIdx.x;
    int k    = gtid >> 5;
    int lane = gtid & 31;
    if (k < K_CODES) {
        const float* e = emb + (size_t)k * D_DIM;
        float p1 = __fmul_rn(e[lane],      e[lane]);
        float p2 = __fmul_rn(e[lane + 32], e[lane + 32]);
        float t  = __fadd_rn(p1, p2);
#pragma unroll
        for (int off = 16; off >= 1; off >>= 1)
            t = __fadd_rn(t, __shfl_down_sync(0xFFFFFFFFu, t, off));
        if (lane == 0) {
            g_b2[k] = t;
            g_counts[k] = 0;
        }
    }
    if (gtid == 0) g_loss = 0.0f;
}

// ---------------------------------------------------------------------------
// Kernel 2: fused distance + argmin, packed f32x2, 2 rows/thread.
// Score bitwise-identical to reference: dist = fl(fl(a2 - 2*dot) + b2),
// dot = sequential fma chain d=0..63, a2 = XLA warp-tree order.
// ---------------------------------------------------------------------------
__global__ __launch_bounds__(THREADS, 1)
void vq_main(const float* __restrict__ z, const float* __restrict__ emb,
             float* __restrict__ out, int out_size) {
    __shared__ float se_t[D_DIM][TK];   // transposed tile: [dim][code], 32 KB
    __shared__ float sb2[TK];

    const int tid  = threadIdx.x;
    const int row0 = blockIdx.x * THREADS + tid;          // rows [0, 16384)
    const int row1 = row0 + N_ROWS / 2;                   // rows [16384, 32768)

    // load both z rows (coalesced: hw varies across threads)
    float zr0[D_DIM], zr1[D_DIM];
    {
        const int b0 = row0 >> 12, hw0 = row0 & 4095;
        const int b1 = row1 >> 12, hw1 = row1 & 4095;
        const float* zb0 = z + (size_t)b0 * (D_DIM * HW) + hw0;
        const float* zb1 = z + (size_t)b1 * (D_DIM * HW) + hw1;
#pragma unroll
        for (int d = 0; d < D_DIM; d++) { zr0[d] = zb0[(size_t)d * HW]; zr1[d] = zb1[(size_t)d * HW]; }
    }

    // a2 per row, XLA warp-tree order (in-register emulation)
    float a2_0, a2_1;
    {
        float t0[32], t1[32];
#pragma unroll
        for (int l = 0; l < 32; l++) {
            t0[l] = __fadd_rn(__fmul_rn(zr0[l], zr0[l]), __fmul_rn(zr0[l + 32], zr0[l + 32]));
            t1[l] = __fadd_rn(__fmul_rn(zr1[l], zr1[l]), __fmul_rn(zr1[l + 32], zr1[l + 32]));
        }
#pragma unroll
        for (int off = 16; off >= 1; off >>= 1)
#pragma unroll
            for (int l = 0; l < 16; l++)
                if (l < off) {
                    t0[l] = __fadd_rn(t0[l], t0[l + off]);
                    t1[l] = __fadd_rn(t1[l], t1[l + off]);
                }
        a2_0 = t0[0]; a2_1 = t1[0];
    }
    const ull a2p0 = pack2(a2_0, a2_0);
    const ull a2p1 = pack2(a2_1, a2_1);
    const ull NEG2 = pack2(-2.0f, -2.0f);

    float best0 = 3.4e38f, best1 = 3.4e38f;
    int   bidx0 = 0,       bidx1 = 0;

    for (int k0 = 0; k0 < K_CODES; k0 += TK) {
        __syncthreads();
        // tile load: thread owns code column (k0+tid); STS conflict-free per d-row
        {
            const float4* g = reinterpret_cast<const float4*>(emb + (size_t)(k0 + tid) * D_DIM);
#pragma unroll
            for (int j = 0; j < D_DIM / 4; j++) {
                float4 v = g[j];
                se_t[4 * j + 0][tid] = v.x;
                se_t[4 * j + 1][tid] = v.y;
                se_t[4 * j + 2][tid] = v.z;
                se_t[4 * j + 3][tid] = v.w;
            }
            sb2[tid] = g_b2[k0 + tid];
        }
        __syncthreads();

#pragma unroll 1
        for (int kk = 0; kk < TK; kk += 16) {
            ull acc0[8], acc1[8];
#pragma unroll
            for (int p = 0; p < 8; p++) { acc0[p] = 0ULL; acc1[p] = 0ULL; }

#pragma unroll 8
            for (int d = 0; d < D_DIM; d++) {
                const ull zp0 = pack2(zr0[d], zr0[d]);
                const ull zp1 = pack2(zr1[d], zr1[d]);
                const ulonglong2* ep = reinterpret_cast<const ulonglong2*>(&se_t[d][kk]);
#pragma unroll
                for (int g = 0; g < 4; g++) {
                    ulonglong2 e = ep[g];          // codes kk+4g .. kk+4g+3 at dim d
                    FMA2(acc0[2 * g + 0], zp0, e.x);
                    FMA2(acc0[2 * g + 1], zp0, e.y);
                    FMA2(acc1[2 * g + 0], zp1, e.x);
                    FMA2(acc1[2 * g + 1], zp1, e.y);
                }
            }

            // dist = fl(fl(a2 - 2*dot) + b2): fma(-2,dot,a2) is exact-equal to
            // sub(a2, 2*dot) since 2*dot is exact.
            const ull* b2p = reinterpret_cast<const ull*>(&sb2[kk]);
#pragma unroll
            for (int p = 0; p < 8; p++) {
                ull bb = b2p[p];
                ull d0p = add2v(fma2v(acc0[p], NEG2, a2p0), bb);
                ull d1p = add2v(fma2v(acc1[p], NEG2, a2p1), bb);
                float dl, dh;
                unpack2(dl, dh, d0p);
                if (dl < best0) { best0 = dl; bidx0 = k0 + kk + 2 * p + 0; }
                if (dh < best0) { best0 = dh; bidx0 = k0 + kk + 2 * p + 1; }
                unpack2(dl, dh, d1p);
                if (dl < best1) { best1 = dl; bidx1 = k0 + kk + 2 * p + 0; }
                if (dh < best1) { best1 = dh; bidx1 = k0 + kk + 2 * p + 1; }
            }
        }
    }

    // gather + STE z_q + loss partials for both rows
    float ssq = 0.0f;
    const bool write_zq = (out_size >= NZ);
    {
        const int b0 = row0 >> 12, hw0 = row0 & 4095;
        const float* eb = emb + (size_t)bidx0 * D_DIM;
        float* zqb = out + (size_t)b0 * (D_DIM * HW) + hw0;
#pragma unroll
        for (int d = 0; d < D_DIM; d++) {
            float ev = eb[d];
            float df = __fsub_rn(zr0[d], ev);
            ssq = fmaf(df, df, ssq);
            if (write_zq) zqb[(size_t)d * HW] = __fadd_rn(zr0[d], __fsub_rn(ev, zr0[d]));
        }
    }
    {
        const int b1 = row1 >> 12, hw1 = row1 & 4095;
        const float* eb = emb + (size_t)bidx1 * D_DIM;
        float* zqb = out + (size_t)b1 * (D_DIM * HW) + hw1;
#pragma unroll
        for (int d = 0; d < D_DIM; d++) {
            float ev = eb[d];
            float df = __fsub_rn(zr1[d], ev);
            ssq = fmaf(df, df, ssq);
            if (write_zq) zqb[(size_t)d * HW] = __fadd_rn(zr1[d], __fsub_rn(ev, zr1[d]));
        }
    }

    if (out_size >= NZ + NI) {
        out[NZ + row0] = (float)bidx0;
        out[NZ + row1] = (float)bidx1;
    }
    atomicAdd(&g_counts[bidx0], 1);
    atomicAdd(&g_counts[bidx1], 1);

#pragma unroll
    for (int o = 16; o > 0; o >>= 1) ssq += __shfl_down_sync(0xFFFFFFFFu, ssq, o);
    if ((tid & 31) == 0) atomicAdd(&g_loss, ssq);
}

// ---------------------------------------------------------------------------
// Kernel 3: scalars (commit_loss, perplexity, usage)
// ---------------------------------------------------------------------------
__global__ void vq_finalize(float* __restrict__ out, int out_size) {
    __shared__ float sH[256];
    __shared__ int   sU[256];
    const int tid = threadIdx.x;
    float H = 0.0f;
    int used = 0;
    for (int k = tid; k < K_CODES; k += 256) {
        float c = (float)g_counts[k];
        if (c > 0.0f) used++;
        float avg = c * (1.0f / (float)N_ROWS);
        H = fmaf(avg, logf(avg + 1e-10f), H);
    }
    sH[tid] = H;
    sU[tid] = used;
    __syncthreads();
    for (int s = 128; s > 0; s >>= 1) {
        if (tid < s) { sH[tid] += sH[tid + s]; sU[tid] += sU[tid + s]; }
        __syncthreads();
    }
    if (tid == 0 && out_size >= NZ + NI + 3) {
        out[NZ + NI + 0] = BETA * g_loss / (float)(N_ROWS * D_DIM);
        out[NZ + NI + 1] = expf(-sH[0]);
        out[NZ + NI + 2] = (float)sU[0] / (float)K_CODES;
    }
}

// ---------------------------------------------------------------------------
extern "C" void kernel_launch(void* const* d_in, const int* in_sizes, int n_in,
                              void* d_out, int out_size) {
    const float* z   = (const float*)d_in[0];
    const float* emb = (const float*)d_in[1];
    float* out = (float*)d_out;

    vq_prep<<<(K_CODES * 32) / 256, 256>>>(emb);
    vq_main<<<N_ROWS / (THREADS * RPT), THREADS>>>(z, emb, out, out_size);
    vq_finalize<<<1, 256>>>(out, out_size);
}

// round 6
// speedup vs baseline: 2.9204x; 2.9204x over previous
#include <cuda_runtime.h>
#include <cuda_bf16.h>
#include <math.h>
#include <stdint.h>

// VanillaVQ: z_e (8,64,64,64) fp32, embedding (8192,64) fp32.
// Outputs (concat fp32): z_q | indices | commit_loss | perplexity | usage.

#define K_CODES 8192
#define D_DIM   64
#define N_ROWS  32768
#define HW      4096
#define BETA    0.25f
#define NZ (N_ROWS * D_DIM)
#define NI N_ROWS
#define EPS_GAP 3e-5f

// GEMM config
#define M_CTA  256
#define CTAS   128
#define NTH    256          // 8 warps: 4(M) x 2(N)
#define NT     64           // codes per N-chunk
#define NCH    128          // chunks
#define KD     192          // padded contraction dims
#define RS     400          // smem row stride (bytes): 400 mod 128 = 16 -> ldmatrix conflict-free
#define SM_A   0
#define SM_B0  102400       // 256*400
#define SM_B1  128000       // +64*400
#define SM_TOT 153600

// ---------------- device scratch ----------------
__device__ float g_b2[K_CODES];
__device__ int   g_counts[K_CODES];
__device__ float g_loss;
__device__ int   g_nflag;
__device__ int   g_idx[N_ROWS];
__device__ int   g_flagrows[N_ROWS];
__device__ float g_a2f[N_ROWS];
__device__ float g_pval[N_ROWS * 64];
__device__ int   g_pidx[N_ROWS * 64];
__device__ __align__(128) uint32_t g_E[K_CODES * (KD / 2)];   // 3MB: rows of 96 u32 (192 bf16)

// ---------------- helpers ----------------
__device__ __forceinline__ uint32_t smem_u32(const void* p) {
    uint32_t a;
    asm("{ .reg .u64 t; cvta.to.shared.u64 t, %1; cvt.u32.u64 %0, t; }" : "=r"(a) : "l"(p));
    return a;
}
__device__ __forceinline__ uint32_t packbf(float a, float b) {
    return (uint32_t)__bfloat16_as_ushort(__float2bfloat16(a))
         | ((uint32_t)__bfloat16_as_ushort(__float2bfloat16(b)) << 16);
}
__device__ __forceinline__ float bfr(float a) { return __bfloat162float(__float2bfloat16(a)); }

__device__ __forceinline__ void ldm_x4(uint32_t* r, uint32_t addr) {
    asm volatile("ldmatrix.sync.aligned.m8n8.x4.shared.b16 {%0,%1,%2,%3}, [%4];"
                 : "=r"(r[0]), "=r"(r[1]), "=r"(r[2]), "=r"(r[3]) : "r"(addr));
}
__device__ __forceinline__ void ldm_x2(uint32_t* r, uint32_t addr) {
    asm volatile("ldmatrix.sync.aligned.m8n8.x2.shared.b16 {%0,%1}, [%2];"
                 : "=r"(r[0]), "=r"(r[1]) : "r"(addr));
}
__device__ __forceinline__ void mma16816(float* c, const uint32_t* a, const uint32_t* b) {
    asm volatile(
        "mma.sync.aligned.m16n8k16.row.col.f32.bf16.bf16.f32 "
        "{%0,%1,%2,%3}, {%4,%5,%6,%7}, {%8,%9}, {%0,%1,%2,%3};"
        : "+f"(c[0]), "+f"(c[1]), "+f"(c[2]), "+f"(c[3])
        : "r"(a[0]), "r"(a[1]), "r"(a[2]), "r"(a[3]), "r"(b[0]), "r"(b[1]));
}
__device__ __forceinline__ void cp16(uint32_t dst, const void* src) {
    uint64_t gs; asm("cvta.to.global.u64 %0, %1;" : "=l"(gs) : "l"(src));
    asm volatile("cp.async.cg.shared.global [%0], [%1], 16;" :: "r"(dst), "l"(gs));
}

// ---------------------------------------------------------------------------
// Kernel 1: b2 in XLA warp-tree order + zero accumulators (warp per code)
// ---------------------------------------------------------------------------
__global__ void vq_prep(const float* __restrict__ emb) {
    int gtid = blockIdx.x * blockDim.x + threadIdx.x;
    int k = gtid >> 5, lane = gtid & 31;
    if (k < K_CODES) {
        const float* e = emb + (size_t)k * D_DIM;
        float t = __fadd_rn(__fmul_rn(e[lane], e[lane]),
                            __fmul_rn(e[lane + 32], e[lane + 32]));
#pragma unroll
        for (int off = 16; off >= 1; off >>= 1)
            t = __fadd_rn(t, __shfl_down_sync(0xFFFFFFFFu, t, off));
        if (lane == 0) { g_b2[k] = t; g_counts[k] = 0; }
    }
    if (gtid == 0) { g_loss = 0.0f; g_nflag = 0; }
}

// ---------------------------------------------------------------------------
// Kernel 2: build B image, row-major [k][192 bf16]: e1 | e1 | e2
// ---------------------------------------------------------------------------
__global__ void vq_prep_e(const float* __restrict__ emb) {
    int k = blockIdx.x * blockDim.x + threadIdx.x;
    if (k >= K_CODES) return;
    uint32_t* base = g_E + (size_t)k * 96;
    const float* e = emb + (size_t)k * D_DIM;
#pragma unroll 8
    for (int j = 0; j < 32; j++) {
        float f0 = e[2 * j], f1 = e[2 * j + 1];
        float h0 = bfr(f0), h1 = bfr(f1);
        uint32_t p = packbf(f0, f1);
        base[j]      = p;                         // e1
        base[32 + j] = p;                         // e1 dup
        base[64 + j] = packbf(f0 - h0, f1 - h1);  // e2
    }
}

// ---------------------------------------------------------------------------
// Kernel 3: HMMA GEMM  S = z1e1 + z2e1 + z1e2  + running top-2 + gap flag
// ---------------------------------------------------------------------------
__device__ __forceinline__ void copy_chunk(int c, uint32_t dstbase, int tid) {
    const char* src = (const char*)g_E + (size_t)c * (NT * 384);
#pragma unroll
    for (int t = 0; t < 6; t++) {
        int idx = tid + t * NTH;                 // 0..1535
        int row = idx / 24, seg = idx % 24;
        cp16(dstbase + (uint32_t)row * RS + (uint32_t)seg * 16,
             src + (size_t)row * 384 + (size_t)seg * 16);
    }
}

__global__ __launch_bounds__(NTH, 1)
void vq_gemm(const float* __restrict__ z) {
    extern __shared__ __align__(128) char smem[];
    const uint32_t sb = smem_u32(smem);
    const int tid = threadIdx.x, cta = blockIdx.x;
    const int lane = tid & 31, warp = tid >> 5;
    const int wm = warp >> 1, wn = warp & 1;      // 4(M) x 2(N)

    // ---- build A tile: row tid, dims [z1(0:63) | z2(64:127) | z1(128:191)] ----
    {
        int grow = cta * M_CTA + tid;
        const float* zp = z + (size_t)(grow >> 12) * (D_DIM * HW) + (grow & 4095);
        char* ar = smem + SM_A + (size_t)tid * RS;
#pragma unroll 8
        for (int d = 0; d < 64; d += 2) {
            float f0 = zp[(size_t)d * HW], f1 = zp[(size_t)(d + 1) * HW];
            float h0 = bfr(f0), h1 = bfr(f1);
            uint32_t p = packbf(f0, f1);
            *(uint32_t*)(ar + 2 * d)       = p;
            *(uint32_t*)(ar + 128 + 2 * d) = packbf(f0 - h0, f1 - h1);
            *(uint32_t*)(ar + 256 + 2 * d) = p;
        }
    }
    __syncthreads();

    // prefetch chunk 0
    copy_chunk(0, sb + SM_B0, tid);
    asm volatile("cp.async.commit_group;");

    // per-thread ldmatrix base addresses
    const uint32_t Abase = sb + SM_A
        + (uint32_t)(wm * 64 + (lane & 7) + ((lane >> 3) & 1) * 8) * RS
        + ((lane >> 4) & 1) * 16;
    const int bl = lane & 15;
    const uint32_t Bofs = (uint32_t)(wn * 32 + (bl & 7)) * RS + ((bl >> 3) & 1) * 16;

    float m1[8], m2[8]; int k1[8];
#pragma unroll
    for (int i = 0; i < 8; i++) { m1[i] = -3.4e38f; m2[i] = -3.4e38f; k1[i] = 0; }

    for (int c = 0; c < NCH; c++) {
        const uint32_t bbase = sb + ((c & 1) ? SM_B1 : SM_B0);
        __syncthreads();                      // all reads of the other buffer done
        if (c + 1 < NCH) copy_chunk(c + 1, sb + ((c & 1) ? SM_B0 : SM_B1), tid);
        asm volatile("cp.async.commit_group;");
        asm volatile("cp.async.wait_group 1;");
        __syncthreads();                      // chunk c visible to all warps

        float acc[4][4][4];
#pragma unroll
        for (int mf = 0; mf < 4; mf++)
#pragma unroll
            for (int nf = 0; nf < 4; nf++)
#pragma unroll
                for (int v = 0; v < 4; v++) acc[mf][nf][v] = 0.0f;

#pragma unroll
        for (int ks = 0; ks < 12; ks++) {
            uint32_t a[4][4], b[4][2];
#pragma unroll
            for (int mf = 0; mf < 4; mf++)
                ldm_x4(a[mf], Abase + (uint32_t)mf * (16 * RS) + (uint32_t)ks * 32);
#pragma unroll
            for (int nf = 0; nf < 4; nf++)
                ldm_x2(b[nf], bbase + Bofs + (uint32_t)nf * (8 * RS) + (uint32_t)ks * 32);
#pragma unroll
            for (int mf = 0; mf < 4; mf++)
#pragma unroll
                for (int nf = 0; nf < 4; nf++)
                    mma16816(acc[mf][nf], a[mf], b[nf]);
        }

        // epilogue: S = acc - 0.5*b2 ; update per-row top-2
#pragma unroll
        for (int nf = 0; nf < 4; nf++) {
            const int ng = c * NT + wn * 32 + nf * 8 + (lane & 3) * 2;
            const float2 bv = *(const float2*)&g_b2[ng];
#pragma unroll
            for (int mf = 0; mf < 4; mf++) {
                float s0 = fmaf(-0.5f, bv.x, acc[mf][nf][0]);
                float s1 = fmaf(-0.5f, bv.y, acc[mf][nf][1]);
                float s2 = fmaf(-0.5f, bv.x, acc[mf][nf][2]);
                float s3 = fmaf(-0.5f, bv.y, acc[mf][nf][3]);
                const int r0 = mf * 2, r1 = mf * 2 + 1;
                if (s0 > m1[r0]) { m2[r0] = m1[r0]; m1[r0] = s0; k1[r0] = ng; }
                else if (s0 > m2[r0]) m2[r0] = s0;
                if (s1 > m1[r0]) { m2[r0] = m1[r0]; m1[r0] = s1; k1[r0] = ng + 1; }
                else if (s1 > m2[r0]) m2[r0] = s1;
                if (s2 > m1[r1]) { m2[r1] = m1[r1]; m1[r1] = s2; k1[r1] = ng; }
                else if (s2 > m2[r1]) m2[r1] = s2;
                if (s3 > m1[r1]) { m2[r1] = m1[r1]; m1[r1] = s3; k1[r1] = ng + 1; }
                else if (s3 > m2[r1]) m2[r1] = s3;
            }
        }
    }

    // merge top-2 across the 4 lanes of each quad (same rows, different cols)
#pragma unroll
    for (int off = 1; off <= 2; off <<= 1) {
#pragma unroll
        for (int i = 0; i < 8; i++) {
            float om1 = __shfl_xor_sync(0xFFFFFFFFu, m1[i], off);
            float om2 = __shfl_xor_sync(0xFFFFFFFFu, m2[i], off);
            int   ok  = __shfl_xor_sync(0xFFFFFFFFu, k1[i], off);
            if (om1 > m1[i]) { m2[i] = fmaxf(m1[i], om2); m1[i] = om1; k1[i] = ok; }
            else             { m2[i] = fmaxf(m2[i], om1); }
        }
    }

    __syncthreads();   // done with A/B smem; reuse for reduction
    float* RM1 = (float*)smem;                 // [256][2]
    float* RM2 = (float*)(smem + 2048);
    int*   RK  = (int*)(smem + 4096);
    if ((lane & 3) == 0) {
#pragma unroll
        for (int mf = 0; mf < 4; mf++)
#pragma unroll
            for (int h = 0; h < 2; h++) {
                int ri = mf * 2 + h;
                int rl = wm * 64 + mf * 16 + h * 8 + (lane >> 2);
                RM1[rl * 2 + wn] = m1[ri];
                RM2[rl * 2 + wn] = m2[ri];
                RK [rl * 2 + wn] = k1[ri];
            }
    }
    __syncthreads();
    {
        int rl = tid;
        float a1v = RM1[rl * 2],     a2v = RM2[rl * 2];     int ak = RK[rl * 2];
        float b1v = RM1[rl * 2 + 1], b2v = RM2[rl * 2 + 1]; int bk = RK[rl * 2 + 1];
        float f1, f2; int fk;
        if (b1v > a1v) { f1 = b1v; fk = bk; f2 = fmaxf(a1v, b2v); }
        else           { f1 = a1v; fk = ak; f2 = fmaxf(a2v, b1v); }
        int grow = cta * M_CTA + rl;
        g_idx[grow] = fk;
        if (f1 - f2 < EPS_GAP) { int p = atomicAdd(&g_nflag, 1); g_flagrows[p] = grow; }
    }
}

// ---------------------------------------------------------------------------
// Kernel 4: exact a2 (XLA shfl tree) for flagged rows — warp per row
// ---------------------------------------------------------------------------
__global__ void vq_a2(const float* __restrict__ z) {
    int nf = g_nflag;
    int gw = (blockIdx.x * blockDim.x + threadIdx.x) >> 5;
    int lane = threadIdx.x & 31;
    int nwarps = (gridDim.x * blockDim.x) >> 5;
    for (int fi = gw; fi < nf; fi += nwarps) {
        int row = g_flagrows[fi];
        const float* zp = z + (size_t)(row >> 12) * (D_DIM * HW) + (row & 4095);
        float v1 = zp[(size_t)lane * HW], v2 = zp[(size_t)(lane + 32) * HW];
        float t = __fadd_rn(__fmul_rn(v1, v1), __fmul_rn(v2, v2));
#pragma unroll
        for (int off = 16; off >= 1; off >>= 1)
            t = __fadd_rn(t, __shfl_down_sync(0xFFFFFFFFu, t, off));
        if (lane == 0) g_a2f[fi] = t;
    }
}

// ---------------------------------------------------------------------------
// Kernel 5: fallback stage A — bit-exact dist per code tile (64 blocks)
// ---------------------------------------------------------------------------
__global__ __launch_bounds__(128)
void vq_fb_part(const float* __restrict__ z, const float* __restrict__ emb) {
    __shared__ float ec[128][68];
    __shared__ float zbuf[2][64];
    __shared__ float b2c[128];
    __shared__ float wv[4];
    __shared__ int   wk[4];
    const int tid = threadIdx.x, t = blockIdx.x;
    const int nf = g_nflag;
    if (nf == 0) return;

    {
        const float4* g = (const float4*)(emb + (size_t)(t * 128 + tid) * D_DIM);
        float4* d = (float4*)&ec[tid][0];
#pragma unroll
        for (int i = 0; i < 16; i++) d[i] = g[i];
        b2c[tid] = g_b2[t * 128 + tid];
    }
    if (tid < 64) {
        int row = g_flagrows[0];
        zbuf[0][tid] = z[(size_t)(row >> 12) * (D_DIM * HW) + (size_t)tid * HW + (row & 4095)];
    }
    __syncthreads();

    for (int fi = 0; fi < nf; fi++) {
        const int par = fi & 1;
        if (tid < 64 && fi + 1 < nf) {
            int row = g_flagrows[fi + 1];
            zbuf[par ^ 1][tid] = z[(size_t)(row >> 12) * (D_DIM * HW) + (size_t)tid * HW + (row & 4095)];
        }
        float acc = 0.0f;
        const float4* zb = (const float4*)&zbuf[par][0];
        const float4* eb = (const float4*)&ec[tid][0];
#pragma unroll
        for (int i = 0; i < 16; i++) {
            float4 zv = zb[i], ev = eb[i];
            acc = fmaf(zv.x, ev.x, acc); acc = fmaf(zv.y, ev.y, acc);
            acc = fmaf(zv.z, ev.z, acc); acc = fmaf(zv.w, ev.w, acc);
        }
        float dist = __fadd_rn(__fsub_rn(g_a2f[fi], __fmul_rn(2.0f, acc)), b2c[tid]);
        int   kidx = t * 128 + tid;
#pragma unroll
        for (int off = 16; off >= 1; off >>= 1) {
            float ov = __shfl_down_sync(0xFFFFFFFFu, dist, off);
            int   ok = __shfl_down_sync(0xFFFFFFFFu, kidx, off);
            if (ov < dist || (ov == dist && ok < kidx)) { dist = ov; kidx = ok; }
        }
        if ((tid & 31) == 0) { wv[tid >> 5] = dist; wk[tid >> 5] = kidx; }
        __syncthreads();
        if (tid == 0) {
            float bv = wv[0]; int bk = wk[0];
#pragma unroll
            for (int w = 1; w < 4; w++)
                if (wv[w] < bv || (wv[w] == bv && wk[w] < bk)) { bv = wv[w]; bk = wk[w]; }
            g_pval[(size_t)fi * 64 + t] = bv;
            g_pidx[(size_t)fi * 64 + t] = bk;
        }
        __syncthreads();
    }
}

// ---------------------------------------------------------------------------
// Kernel 6: fallback stage B — warp per flagged row reduces 64 tile results
// ---------------------------------------------------------------------------
__global__ void vq_fb_red() {
    int nf = g_nflag;
    int gw = (blockIdx.x * blockDim.x + threadIdx.x) >> 5;
    int lane = threadIdx.x & 31;
    int nwarps = (gridDim.x * blockDim.x) >> 5;
    for (int fi = gw; fi < nf; fi += nwarps) {
        float v1 = g_pval[(size_t)fi * 64 + lane];
        int   k1 = g_pidx[(size_t)fi * 64 + lane];
        float v2 = g_pval[(size_t)fi * 64 + lane + 32];
        int   k2 = g_pidx[(size_t)fi * 64 + lane + 32];
        if (v2 < v1 || (v2 == v1 && k2 < k1)) { v1 = v2; k1 = k2; }
#pragma unroll
        for (int off = 16; off >= 1; off >>= 1) {
            float ov = __shfl_down_sync(0xFFFFFFFFu, v1, off);
            int   ok = __shfl_down_sync(0xFFFFFFFFu, k1, off);
            if (ov < v1 || (ov == v1 && ok < k1)) { v1 = ov; k1 = ok; }
        }
        if (lane == 0) g_idx[g_flagrows[fi]] = k1;
    }
}

// ---------------------------------------------------------------------------
// Kernel 7: gather + STE z_q + indices + counts + loss
// ---------------------------------------------------------------------------
__global__ __launch_bounds__(256)
void vq_final(const float* __restrict__ z, const float* __restrict__ emb,
              float* __restrict__ out, int out_size) {
    const int row = blockIdx.x * 256 + threadIdx.x;
    const int b = row >> 12, hw = row & 4095;
    const int bidx = g_idx[row];
    const float* zp = z + (size_t)b * (D_DIM * HW) + hw;
    const float* eb = emb + (size_t)bidx * D_DIM;
    float* zq = out + (size_t)b * (D_DIM * HW) + hw;
    const bool wz = (out_size >= NZ);
    float ssq = 0.0f;
#pragma unroll
    for (int d = 0; d < D_DIM; d++) {
        float zv = zp[(size_t)d * HW], ev = eb[d];
        float df = __fsub_rn(zv, ev);
        ssq = fmaf(df, df, ssq);
        if (wz) zq[(size_t)d * HW] = __fadd_rn(zv, __fsub_rn(ev, zv));
    }
    if (out_size >= NZ + NI) out[NZ + row] = (float)bidx;
    atomicAdd(&g_counts[bidx], 1);
#pragma unroll
    for (int o = 16; o > 0; o >>= 1) ssq += __shfl_down_sync(0xFFFFFFFFu, ssq, o);
    if ((threadIdx.x & 31) == 0) atomicAdd(&g_loss, ssq);
}

// ---------------------------------------------------------------------------
// Kernel 8: scalars
// ---------------------------------------------------------------------------
__global__ void vq_finalize(float* __restrict__ out, int out_size) {
    __shared__ float sH[256];
    __shared__ int   sU[256];
    const int tid = threadIdx.x;
    float H = 0.0f; int used = 0;
    for (int k = tid; k < K_CODES; k += 256) {
        float c = (float)g_counts[k];
        if (c > 0.0f) used++;
        float avg = c * (1.0f / (float)N_ROWS);
        H = fmaf(avg, logf(avg + 1e-10f), H);
    }
    sH[tid] = H; sU[tid] = used;
    __syncthreads();
    for (int s = 128; s > 0; s >>= 1) {
        if (tid < s) { sH[tid] += sH[tid + s]; sU[tid] += sU[tid + s]; }
        __syncthreads();
    }
    if (tid == 0 && out_size >= NZ + NI + 3) {
        out[NZ + NI + 0] = BETA * g_loss / (float)(N_ROWS * D_DIM);
        out[NZ + NI + 1] = expf(-sH[0]);
        out[NZ + NI + 2] = (float)sU[0] / (float)K_CODES;
    }
}

// ---------------------------------------------------------------------------
extern "C" void kernel_launch(void* const* d_in, const int* in_sizes, int n_in,
                              void* d_out, int out_size) {
    const float* z   = (const float*)d_in[0];
    const float* emb = (const float*)d_in[1];
    float* out = (float*)d_out;

    cudaFuncSetAttribute(vq_gemm, cudaFuncAttributeMaxDynamicSharedMemorySize, SM_TOT);

    vq_prep<<<(K_CODES * 32) / 256, 256>>>(emb);
    vq_prep_e<<<K_CODES / 256, 256>>>(emb);
    vq_gemm<<<CTAS, NTH, SM_TOT>>>(z);
    vq_a2<<<64, 256>>>(z);
    vq_fb_part<<<64, 128>>>(z, emb);
    vq_fb_red<<<64, 256>>>();
    vq_final<<<N_ROWS / 256, 256>>>(z, emb, out, out_size);
    vq_finalize<<<1, 256>>>(out, out_size);
}

// round 7
// speedup vs baseline: 2.9752x; 1.0188x over previous
#include <cuda_runtime.h>
#include <cuda_bf16.h>
#include <math.h>
#include <stdint.h>

// VanillaVQ: z_e (8,64,64,64) fp32, embedding (8192,64) fp32.
// Outputs (concat fp32): z_q | indices | commit_loss | perplexity | usage.

#define K_CODES 8192
#define D_DIM   64
#define N_ROWS  32768
#define HW      4096
#define BETA    0.25f
#define NZ (N_ROWS * D_DIM)
#define NI N_ROWS
#define EPS_GAP 8e-4f

// GEMM config: S = [z1|z2] . [e1|e1] = z . bf16(e)   (KD=128)
#define M_CTA  256
#define CTAS   128
#define NTH    512          // 16 warps: 4(M) x 4(N)
#define NT     128          // codes per chunk
#define NCH    64
#define ARS    272          // A row stride bytes (16 mod 128 -> conflict-free ldmatrix)
#define BRS    144          // B row stride bytes
#define SM_A   0
#define SM_B0  69632        // 256*272
#define SM_B1  88064        // +128*144
#define SM_TOT 106496

// ---------------- device scratch ----------------
__device__ float g_b2[K_CODES];
__device__ int   g_counts[K_CODES];
__device__ float g_loss;
__device__ int   g_nflag;
__device__ int   g_idx[N_ROWS];
__device__ int   g_flagrows[N_ROWS];
__device__ float g_a2f[N_ROWS];
__device__ float g_pval[N_ROWS * 64];
__device__ int   g_pidx[N_ROWS * 64];
__device__ __align__(128) uint32_t g_E[K_CODES * 32];   // 1MB bf16 image of emb

// ---------------- helpers ----------------
__device__ __forceinline__ uint32_t smem_u32(const void* p) {
    uint32_t a;
    asm("{ .reg .u64 t; cvta.to.shared.u64 t, %1; cvt.u32.u64 %0, t; }" : "=r"(a) : "l"(p));
    return a;
}
__device__ __forceinline__ uint32_t packbf(float a, float b) {
    return (uint32_t)__bfloat16_as_ushort(__float2bfloat16(a))
         | ((uint32_t)__bfloat16_as_ushort(__float2bfloat16(b)) << 16);
}
__device__ __forceinline__ float bfr(float a) { return __bfloat162float(__float2bfloat16(a)); }
__device__ __forceinline__ void ldm_x4(uint32_t* r, uint32_t addr) {
    asm volatile("ldmatrix.sync.aligned.m8n8.x4.shared.b16 {%0,%1,%2,%3}, [%4];"
                 : "=r"(r[0]), "=r"(r[1]), "=r"(r[2]), "=r"(r[3]) : "r"(addr));
}
__device__ __forceinline__ void ldm_x2(uint32_t* r, uint32_t addr) {
    asm volatile("ldmatrix.sync.aligned.m8n8.x2.shared.b16 {%0,%1}, [%2];"
                 : "=r"(r[0]), "=r"(r[1]) : "r"(addr));
}
__device__ __forceinline__ void mma16816(float* c, const uint32_t* a, const uint32_t* b) {
    asm volatile(
        "mma.sync.aligned.m16n8k16.row.col.f32.bf16.bf16.f32 "
        "{%0,%1,%2,%3}, {%4,%5,%6,%7}, {%8,%9}, {%0,%1,%2,%3};"
        : "+f"(c[0]), "+f"(c[1]), "+f"(c[2]), "+f"(c[3])
        : "r"(a[0]), "r"(a[1]), "r"(a[2]), "r"(a[3]), "r"(b[0]), "r"(b[1]));
}
__device__ __forceinline__ void cp16(uint32_t dst, const void* src) {
    uint64_t gs; asm("cvta.to.global.u64 %0, %1;" : "=l"(gs) : "l"(src));
    asm volatile("cp.async.cg.shared.global [%0], [%1], 16;" :: "r"(dst), "l"(gs));
}

// ---------------------------------------------------------------------------
// Kernel 1: b2 in XLA warp-tree order + zero accumulators (warp per code)
// ---------------------------------------------------------------------------
__global__ void vq_prep(const float* __restrict__ emb) {
    int gtid = blockIdx.x * blockDim.x + threadIdx.x;
    int k = gtid >> 5, lane = gtid & 31;
    if (k < K_CODES) {
        const float* e = emb + (size_t)k * D_DIM;
        float t = __fadd_rn(__fmul_rn(e[lane], e[lane]),
                            __fmul_rn(e[lane + 32], e[lane + 32]));
#pragma unroll
        for (int off = 16; off >= 1; off >>= 1)
            t = __fadd_rn(t, __shfl_down_sync(0xFFFFFFFFu, t, off));
        if (lane == 0) { g_b2[k] = t; g_counts[k] = 0; }
    }
    if (gtid == 0) { g_loss = 0.0f; g_nflag = 0; }
}

// ---------------------------------------------------------------------------
// Kernel 2: bf16 image of emb (64 bf16 per code)
// ---------------------------------------------------------------------------
__global__ void vq_prep_e(const float* __restrict__ emb) {
    int k = blockIdx.x * blockDim.x + threadIdx.x;
    if (k >= K_CODES) return;
    uint32_t* base = g_E + (size_t)k * 32;
    const float* e = emb + (size_t)k * D_DIM;
#pragma unroll 8
    for (int j = 0; j < 32; j++)
        base[j] = packbf(e[2 * j], e[2 * j + 1]);
}

// ---------------------------------------------------------------------------
// Kernel 3: HMMA GEMM  S = z.bf16(e) - 0.5*b2  + running top-2 + gap flag
// 128 CTAs x 512 threads (warps 4M x 4N); warp tile 64x32; KD=128 via A=[z1|z2].
// ---------------------------------------------------------------------------
__device__ __forceinline__ void copy_chunk(int c, uint32_t dstbase, int tid) {
    const char* src = (const char*)g_E + (size_t)c * (NT * 128);
#pragma unroll
    for (int t = 0; t < 2; t++) {
        int idx = tid + t * NTH;                 // 0..1023
        int row = idx >> 3, seg = idx & 7;
        cp16(dstbase + (uint32_t)row * BRS + (uint32_t)seg * 16,
             src + (size_t)row * 128 + (size_t)seg * 16);
    }
}

__global__ __launch_bounds__(NTH, 1)
void vq_gemm(const float* __restrict__ z) {
    extern __shared__ __align__(128) char smem[];
    const uint32_t sb = smem_u32(smem);
    const int tid = threadIdx.x, cta = blockIdx.x;
    const int lane = tid & 31, warp = tid >> 5;
    const int wm = warp >> 2, wn = warp & 3;      // 4(M) x 4(N)

    // ---- build A tile: row r (<256): bytes [0:128)=z1, [128:256)=z2 ----
    if (tid < M_CTA) {
        int grow = cta * M_CTA + tid;
        const float* zp = z + (size_t)(grow >> 12) * (D_DIM * HW) + (grow & 4095);
        char* ar = smem + SM_A + (size_t)tid * ARS;
#pragma unroll 8
        for (int d = 0; d < 64; d += 2) {
            float f0 = zp[(size_t)d * HW], f1 = zp[(size_t)(d + 1) * HW];
            float h0 = bfr(f0), h1 = bfr(f1);
            *(uint32_t*)(ar + 2 * d)       = packbf(f0, f1);
            *(uint32_t*)(ar + 128 + 2 * d) = packbf(f0 - h0, f1 - h1);
        }
    }
    __syncthreads();

    copy_chunk(0, sb + SM_B0, tid);
    asm volatile("cp.async.commit_group;");

    const uint32_t Abase = sb + SM_A
        + (uint32_t)(wm * 64 + (lane & 7) + ((lane >> 3) & 1) * 8) * ARS
        + ((lane >> 4) & 1) * 16;
    const int bl = lane & 15;
    const uint32_t Bofs = (uint32_t)(wn * 32 + (bl & 7)) * BRS + ((bl >> 3) & 1) * 16;

    float m1[8], m2[8]; int k1[8];
#pragma unroll
    for (int i = 0; i < 8; i++) { m1[i] = -3.4e38f; m2[i] = -3.4e38f; k1[i] = 0; }

    for (int c = 0; c < NCH; c++) {
        const uint32_t bbase = sb + ((c & 1) ? SM_B1 : SM_B0);
        __syncthreads();
        if (c + 1 < NCH) {
            copy_chunk(c + 1, sb + ((c & 1) ? SM_B0 : SM_B1), tid);
            asm volatile("cp.async.commit_group;");
            asm volatile("cp.async.wait_group 1;");
        } else {
            asm volatile("cp.async.wait_group 0;");
        }
        __syncthreads();

        float acc[4][4][4];
#pragma unroll
        for (int mf = 0; mf < 4; mf++)
#pragma unroll
            for (int nf = 0; nf < 4; nf++)
#pragma unroll
                for (int v = 0; v < 4; v++) acc[mf][nf][v] = 0.0f;

#pragma unroll
        for (int kk = 0; kk < 4; kk++) {
            uint32_t b[4][2];
#pragma unroll
            for (int nf = 0; nf < 4; nf++)
                ldm_x2(b[nf], bbase + Bofs + (uint32_t)nf * (8 * BRS) + (uint32_t)kk * 32);
#pragma unroll
            for (int s = 0; s < 2; s++) {
                uint32_t a[4][4];
#pragma unroll
                for (int mf = 0; mf < 4; mf++)
                    ldm_x4(a[mf], Abase + (uint32_t)mf * (16 * ARS)
                                        + (uint32_t)s * 128 + (uint32_t)kk * 32);
#pragma unroll
                for (int mf = 0; mf < 4; mf++)
#pragma unroll
                    for (int nf = 0; nf < 4; nf++)
                        mma16816(acc[mf][nf], a[mf], b[nf]);
            }
        }

        // epilogue: s = acc - 0.5*b2, per-row top-2
#pragma unroll
        for (int nf = 0; nf < 4; nf++) {
            const int ng = c * NT + wn * 32 + nf * 8 + (lane & 3) * 2;
            const float2 bv = *(const float2*)&g_b2[ng];
#pragma unroll
            for (int mf = 0; mf < 4; mf++) {
                float s0 = fmaf(-0.5f, bv.x, acc[mf][nf][0]);
                float s1 = fmaf(-0.5f, bv.y, acc[mf][nf][1]);
                float s2 = fmaf(-0.5f, bv.x, acc[mf][nf][2]);
                float s3 = fmaf(-0.5f, bv.y, acc[mf][nf][3]);
                const int r0 = mf * 2, r1 = mf * 2 + 1;
                if (s0 > m1[r0]) { m2[r0] = m1[r0]; m1[r0] = s0; k1[r0] = ng; }
                else if (s0 > m2[r0]) m2[r0] = s0;
                if (s1 > m1[r0]) { m2[r0] = m1[r0]; m1[r0] = s1; k1[r0] = ng + 1; }
                else if (s1 > m2[r0]) m2[r0] = s1;
                if (s2 > m1[r1]) { m2[r1] = m1[r1]; m1[r1] = s2; k1[r1] = ng; }
                else if (s2 > m2[r1]) m2[r1] = s2;
                if (s3 > m1[r1]) { m2[r1] = m1[r1]; m1[r1] = s3; k1[r1] = ng + 1; }
                else if (s3 > m2[r1]) m2[r1] = s3;
            }
        }
    }

    // merge across the 4 quad lanes (same rows, different cols)
#pragma unroll
    for (int off = 1; off <= 2; off <<= 1) {
#pragma unroll
        for (int i = 0; i < 8; i++) {
            float om1 = __shfl_xor_sync(0xFFFFFFFFu, m1[i], off);
            float om2 = __shfl_xor_sync(0xFFFFFFFFu, m2[i], off);
            int   ok  = __shfl_xor_sync(0xFFFFFFFFu, k1[i], off);
            if (om1 > m1[i]) { m2[i] = fmaxf(m1[i], om2); m1[i] = om1; k1[i] = ok; }
            else             { m2[i] = fmaxf(m2[i], om1); }
        }
    }

    __syncthreads();   // smem reuse for cross-warp reduction
    float* RM1 = (float*)smem;                 // [256][4]
    float* RM2 = (float*)(smem + 4096);
    int*   RK  = (int*)(smem + 8192);
    if ((lane & 3) == 0) {
#pragma unroll
        for (int mf = 0; mf < 4; mf++)
#pragma unroll
            for (int h = 0; h < 2; h++) {
                int ri = mf * 2 + h;
                int rl = wm * 64 + mf * 16 + h * 8 + (lane >> 2);
                RM1[rl * 4 + wn] = m1[ri];
                RM2[rl * 4 + wn] = m2[ri];
                RK [rl * 4 + wn] = k1[ri];
            }
    }
    __syncthreads();
    if (tid < M_CTA) {
        float f1 = RM1[tid * 4], f2 = RM2[tid * 4]; int fk = RK[tid * 4];
#pragma unroll
        for (int w = 1; w < 4; w++) {
            float o1 = RM1[tid * 4 + w], o2 = RM2[tid * 4 + w]; int ok = RK[tid * 4 + w];
            if (o1 > f1) { f2 = fmaxf(f1, o2); f1 = o1; fk = ok; }
            else         { f2 = fmaxf(f2, o1); }
        }
        int grow = cta * M_CTA + tid;
        g_idx[grow] = fk;
        if (f1 - f2 < EPS_GAP) { int p = atomicAdd(&g_nflag, 1); g_flagrows[p] = grow; }
    }
}

// ---------------------------------------------------------------------------
// Kernel 4: exact a2 (XLA shfl tree) for flagged rows — warp per row
// ---------------------------------------------------------------------------
__global__ void vq_a2(const float* __restrict__ z) {
    int nf = g_nflag;
    int gw = (blockIdx.x * blockDim.x + threadIdx.x) >> 5;
    int lane = threadIdx.x & 31;
    int nwarps = (gridDim.x * blockDim.x) >> 5;
    for (int fi = gw; fi < nf; fi += nwarps) {
        int row = g_flagrows[fi];
        const float* zp = z + (size_t)(row >> 12) * (D_DIM * HW) + (row & 4095);
        float v1 = zp[(size_t)lane * HW], v2 = zp[(size_t)(lane + 32) * HW];
        float t = __fadd_rn(__fmul_rn(v1, v1), __fmul_rn(v2, v2));
#pragma unroll
        for (int off = 16; off >= 1; off >>= 1)
            t = __fadd_rn(t, __shfl_down_sync(0xFFFFFFFFu, t, off));
        if (lane == 0) g_a2f[fi] = t;
    }
}

// ---------------------------------------------------------------------------
// Kernel 5: parallel fallback — grid (64 tiles, 8 row-groups), bit-exact dist
// ---------------------------------------------------------------------------
__global__ __launch_bounds__(128)
void vq_fb_part(const float* __restrict__ z, const float* __restrict__ emb) {
    __shared__ float ec[128][68];
    __shared__ float zrow[64];
    __shared__ float b2c[128];
    __shared__ float wv[4];
    __shared__ int   wk[4];
    const int tid = threadIdx.x, t = blockIdx.x, grp = blockIdx.y;
    const int nf = g_nflag;

    {
        const float4* g = (const float4*)(emb + (size_t)(t * 128 + tid) * D_DIM);
        float4* d = (float4*)&ec[tid][0];
#pragma unroll
        for (int i = 0; i < 16; i++) d[i] = g[i];
        b2c[tid] = g_b2[t * 128 + tid];
    }
    __syncthreads();

    for (int fi = grp; fi < nf; fi += 8) {
        if (tid < 64) {
            int row = g_flagrows[fi];
            zrow[tid] = z[(size_t)(row >> 12) * (D_DIM * HW) + (size_t)tid * HW + (row & 4095)];
        }
        __syncthreads();
        float acc = 0.0f;
        const float4* zb = (const float4*)&zrow[0];
        const float4* eb = (const float4*)&ec[tid][0];
#pragma unroll
        for (int i = 0; i < 16; i++) {
            float4 zv = zb[i], ev = eb[i];
            acc = fmaf(zv.x, ev.x, acc); acc = fmaf(zv.y, ev.y, acc);
            acc = fmaf(zv.z, ev.z, acc); acc = fmaf(zv.w, ev.w, acc);
        }
        float dist = __fadd_rn(__fsub_rn(g_a2f[fi], __fmul_rn(2.0f, acc)), b2c[tid]);
        int   kidx = t * 128 + tid;
#pragma unroll
        for (int off = 16; off >= 1; off >>= 1) {
            float ov = __shfl_down_sync(0xFFFFFFFFu, dist, off);
            int   ok = __shfl_down_sync(0xFFFFFFFFu, kidx, off);
            if (ov < dist || (ov == dist && ok < kidx)) { dist = ov; kidx = ok; }
        }
        if ((tid & 31) == 0) { wv[tid >> 5] = dist; wk[tid >> 5] = kidx; }
        __syncthreads();
        if (tid == 0) {
            float bv = wv[0]; int bk = wk[0];
#pragma unroll
            for (int w = 1; w < 4; w++)
                if (wv[w] < bv || (wv[w] == bv && wk[w] < bk)) { bv = wv[w]; bk = wk[w]; }
            g_pval[(size_t)fi * 64 + t] = bv;
            g_pidx[(size_t)fi * 64 + t] = bk;
        }
        __syncthreads();
    }
}

// ---------------------------------------------------------------------------
// Kernel 6: fallback reduce — warp per flagged row over 64 tile results
// ---------------------------------------------------------------------------
__global__ void vq_fb_red() {
    int nf = g_nflag;
    int gw = (blockIdx.x * blockDim.x + threadIdx.x) >> 5;
    int lane = threadIdx.x & 31;
    int nwarps = (gridDim.x * blockDim.x) >> 5;
    for (int fi = gw; fi < nf; fi += nwarps) {
        float v1 = g_pval[(size_t)fi * 64 + lane];
        int   k1 = g_pidx[(size_t)fi * 64 + lane];
        float v2 = g_pval[(size_t)fi * 64 + lane + 32];
        int   k2 = g_pidx[(size_t)fi * 64 + lane + 32];
        if (v2 < v1 || (v2 == v1 && k2 < k1)) { v1 = v2; k1 = k2; }
#pragma unroll
        for (int off = 16; off >= 1; off >>= 1) {
            float ov = __shfl_down_sync(0xFFFFFFFFu, v1, off);
            int   ok = __shfl_down_sync(0xFFFFFFFFu, k1, off);
            if (ov < v1 || (ov == v1 && ok < k1)) { v1 = ov; k1 = ok; }
        }
        if (lane == 0) g_idx[g_flagrows[fi]] = k1;
    }
}

// ---------------------------------------------------------------------------
// Kernel 7: gather + STE z_q + indices + counts + loss
// ---------------------------------------------------------------------------
__global__ __launch_bounds__(256)
void vq_final(const float* __restrict__ z, const float* __restrict__ emb,
              float* __restrict__ out, int out_size) {
    const int row = blockIdx.x * 256 + threadIdx.x;
    const int b = row >> 12, hw = row & 4095;
    const int bidx = g_idx[row];
    const float* zp = z + (size_t)b * (D_DIM * HW) + hw;
    const float* eb = emb + (size_t)bidx * D_DIM;
    float* zq = out + (size_t)b * (D_DIM * HW) + hw;
    const bool wz = (out_size >= NZ);
    float ssq = 0.0f;
#pragma unroll
    for (int d = 0; d < D_DIM; d++) {
        float zv = zp[(size_t)d * HW], ev = eb[d];
        float df = __fsub_rn(zv, ev);
        ssq = fmaf(df, df, ssq);
        if (wz) zq[(size_t)d * HW] = __fadd_rn(zv, __fsub_rn(ev, zv));
    }
    if (out_size >= NZ + NI) out[NZ + row] = (float)bidx;
    atomicAdd(&g_counts[bidx], 1);
#pragma unroll
    for (int o = 16; o > 0; o >>= 1) ssq += __shfl_down_sync(0xFFFFFFFFu, ssq, o);
    if ((threadIdx.x & 31) == 0) atomicAdd(&g_loss, ssq);
}

// ---------------------------------------------------------------------------
// Kernel 8: scalars
// ---------------------------------------------------------------------------
__global__ void vq_finalize(float* __restrict__ out, int out_size) {
    __shared__ float sH[256];
    __shared__ int   sU[256];
    const int tid = threadIdx.x;
    float H = 0.0f; int used = 0;
    for (int k = tid; k < K_CODES; k += 256) {
        float c = (float)g_counts[k];
        if (c > 0.0f) used++;
        float avg = c * (1.0f / (float)N_ROWS);
        H = fmaf(avg, logf(avg + 1e-10f), H);
    }
    sH[tid] = H; sU[tid] = used;
    __syncthreads();
    for (int s = 128; s > 0; s >>= 1) {
        if (tid < s) { sH[tid] += sH[tid + s]; sU[tid] += sU[tid + s]; }
        __syncthreads();
    }
    if (tid == 0 && out_size >= NZ + NI + 3) {
        out[NZ + NI + 0] = BETA * g_loss / (float)(N_ROWS * D_DIM);
        out[NZ + NI + 1] = expf(-sH[0]);
        out[NZ + NI + 2] = (float)sU[0] / (float)K_CODES;
    }
}

// ---------------------------------------------------------------------------
extern "C" void kernel_launch(void* const* d_in, const int* in_sizes, int n_in,
                              void* d_out, int out_size) {
    const float* z   = (const float*)d_in[0];
    const float* emb = (const float*)d_in[1];
    float* out = (float*)d_out;

    cudaFuncSetAttribute(vq_gemm, cudaFuncAttributeMaxDynamicSharedMemorySize, SM_TOT);

    vq_prep<<<(K_CODES * 32) / 256, 256>>>(emb);
    vq_prep_e<<<K_CODES / 256, 256>>>(emb);
    vq_gemm<<<CTAS, NTH, SM_TOT>>>(z);
    vq_a2<<<128, 256>>>(z);
    vq_fb_part<<<dim3(64, 8), 128>>>(z, emb);
    vq_fb_red<<<64, 256>>>();
    vq_final<<<N_ROWS / 256, 256>>>(z, emb, out, out_size);
    vq_finalize<<<1, 256>>>(out, out_size);
}

// round 8
// speedup vs baseline: 3.9302x; 1.3210x over previous
#include <cuda_runtime.h>
#include <cuda_fp16.h>
#include <math.h>
#include <stdint.h>

// VanillaVQ: z_e (8,64,64,64) fp32, embedding (8192,64) fp32.
// Outputs (concat fp32): z_q | indices | commit_loss | perplexity | usage.

#define K_CODES 8192
#define D_DIM   64
#define N_ROWS  32768
#define HW      4096
#define BETA    0.25f
#define NZ (N_ROWS * D_DIM)
#define NI N_ROWS
#define EPS_GAP 5e-4f

// GEMM config: S = fp16(z) . fp16(e)   (KD=64, single precision level, certified)
#define M_CTA  256
#define CTAS   128
#define NTH    512          // 16 warps: 4(M) x 4(N)
#define NT     128          // codes per chunk
#define NCH    64
#define ARS    144          // A row stride bytes (16 mod 128 -> conflict-free ldmatrix)
#define BRS    144          // B row stride bytes
#define SM_A   0            // 256*144 = 36864
#define SM_B(i) (36864u + (uint32_t)(i) * 18432u)   // 3 bufs of 128*144
#define SM_TOT 92160

// ---------------- device scratch ----------------
__device__ float g_b2[K_CODES];
__device__ int   g_counts[K_CODES];
__device__ float g_loss;
__device__ int   g_nflag;
__device__ int   g_idx[N_ROWS];
__device__ int   g_flagrows[N_ROWS];
__device__ float g_a2f[N_ROWS];
__device__ float g_pval[N_ROWS * 64];
__device__ int   g_pidx[N_ROWS * 64];
__device__ __align__(128) uint32_t g_E[K_CODES * 32];   // 1MB fp16 image of emb

// ---------------- helpers ----------------
__device__ __forceinline__ uint32_t smem_u32(const void* p) {
    uint32_t a;
    asm("{ .reg .u64 t; cvta.to.shared.u64 t, %1; cvt.u32.u64 %0, t; }" : "=r"(a) : "l"(p));
    return a;
}
__device__ __forceinline__ uint32_t packh(float a, float b) {
    __half2 h = __floats2half2_rn(a, b);
    return *reinterpret_cast<uint32_t*>(&h);
}
__device__ __forceinline__ void ldm_x4(uint32_t* r, uint32_t addr) {
    asm volatile("ldmatrix.sync.aligned.m8n8.x4.shared.b16 {%0,%1,%2,%3}, [%4];"
                 : "=r"(r[0]), "=r"(r[1]), "=r"(r[2]), "=r"(r[3]) : "r"(addr));
}
__device__ __forceinline__ void ldm_x2(uint32_t* r, uint32_t addr) {
    asm volatile("ldmatrix.sync.aligned.m8n8.x2.shared.b16 {%0,%1}, [%2];"
                 : "=r"(r[0]), "=r"(r[1]) : "r"(addr));
}
__device__ __forceinline__ void mma16816(float* c, const uint32_t* a, const uint32_t* b) {
    asm volatile(
        "mma.sync.aligned.m16n8k16.row.col.f32.f16.f16.f32 "
        "{%0,%1,%2,%3}, {%4,%5,%6,%7}, {%8,%9}, {%0,%1,%2,%3};"
        : "+f"(c[0]), "+f"(c[1]), "+f"(c[2]), "+f"(c[3])
        : "r"(a[0]), "r"(a[1]), "r"(a[2]), "r"(a[3]), "r"(b[0]), "r"(b[1]));
}
__device__ __forceinline__ void cp16(uint32_t dst, const void* src) {
    uint64_t gs; asm("cvta.to.global.u64 %0, %1;" : "=l"(gs) : "l"(src));
    asm volatile("cp.async.cg.shared.global [%0], [%1], 16;" :: "r"(dst), "l"(gs));
}

// ---------------------------------------------------------------------------
// Kernel 1: b2 in XLA warp-tree order + zero accumulators (warp per code)
// ---------------------------------------------------------------------------
__global__ void vq_prep(const float* __restrict__ emb) {
    int gtid = blockIdx.x * blockDim.x + threadIdx.x;
    int k = gtid >> 5, lane = gtid & 31;
    if (k < K_CODES) {
        const float* e = emb + (size_t)k * D_DIM;
        float t = __fadd_rn(__fmul_rn(e[lane], e[lane]),
                            __fmul_rn(e[lane + 32], e[lane + 32]));
#pragma unroll
        for (int off = 16; off >= 1; off >>= 1)
            t = __fadd_rn(t, __shfl_down_sync(0xFFFFFFFFu, t, off));
        if (lane == 0) { g_b2[k] = t; g_counts[k] = 0; }
    }
    if (gtid == 0) { g_loss = 0.0f; g_nflag = 0; }
}

// ---------------------------------------------------------------------------
// Kernel 2: fp16 image of emb (64 fp16 per code, 128B row)
// ---------------------------------------------------------------------------
__global__ void vq_prep_e(const float* __restrict__ emb) {
    int k = blockIdx.x * blockDim.x + threadIdx.x;
    if (k >= K_CODES) return;
    uint32_t* base = g_E + (size_t)k * 32;
    const float* e = emb + (size_t)k * D_DIM;
#pragma unroll 8
    for (int j = 0; j < 32; j++)
        base[j] = packh(e[2 * j], e[2 * j + 1]);
}

// ---------------------------------------------------------------------------
// Kernel 3: fp16 HMMA GEMM  S = z.e - 0.5*b2  + running top-2 + gap flag
// 128 CTAs x 512 threads (4M x 4N warps); warp tile 64x32; KD=64; 3-buf pipeline
// ---------------------------------------------------------------------------
__device__ __forceinline__ void copy_chunk(int c, uint32_t dstbase, int tid) {
    const char* src = (const char*)g_E + (size_t)c * (NT * 128);
#pragma unroll
    for (int t = 0; t < 2; t++) {
        int idx = tid + t * NTH;                 // 0..1023
        int row = idx >> 3, seg = idx & 7;
        cp16(dstbase + (uint32_t)row * BRS + (uint32_t)seg * 16,
             src + (size_t)row * 128 + (size_t)seg * 16);
    }
}

__global__ __launch_bounds__(NTH, 1)
void vq_gemm(const float* __restrict__ z) {
    extern __shared__ __align__(128) char smem[];
    const uint32_t sb = smem_u32(smem);
    const int tid = threadIdx.x, cta = blockIdx.x;
    const int lane = tid & 31, warp = tid >> 5;
    const int wm = warp >> 2, wn = warp & 3;      // 4(M) x 4(N)

    // ---- build A tile: row r (<256): 64 fp16 of z ----
    if (tid < M_CTA) {
        int grow = cta * M_CTA + tid;
        const float* zp = z + (size_t)(grow >> 12) * (D_DIM * HW) + (grow & 4095);
        char* ar = smem + SM_A + (size_t)tid * ARS;
#pragma unroll 8
        for (int d = 0; d < 64; d += 2)
            *(uint32_t*)(ar + 2 * d) = packh(zp[(size_t)d * HW], zp[(size_t)(d + 1) * HW]);
    }
    __syncthreads();

    copy_chunk(0, sb + SM_B(0), tid);
    asm volatile("cp.async.commit_group;");
    copy_chunk(1, sb + SM_B(1), tid);
    asm volatile("cp.async.commit_group;");

    const uint32_t Abase = sb + SM_A
        + (uint32_t)(wm * 64 + (lane & 7) + ((lane >> 3) & 1) * 8) * ARS
        + ((lane >> 4) & 1) * 16;
    const int bl = lane & 15;
    const uint32_t Bofs = (uint32_t)(wn * 32 + (bl & 7)) * BRS + ((bl >> 3) & 1) * 16;

    float m1[8], m2[8]; int k1[8];
#pragma unroll
    for (int i = 0; i < 8; i++) { m1[i] = -3.4e38f; m2[i] = -3.4e38f; k1[i] = 0; }

    for (int c = 0; c < NCH; c++) {
        const uint32_t bbase = sb + SM_B(c % 3);
        if (c == NCH - 1) asm volatile("cp.async.wait_group 0;");
        else              asm volatile("cp.async.wait_group 1;");
        __syncthreads();     // chunk c visible; everyone done with buf (c+2)%3
        if (c + 2 < NCH) {
            copy_chunk(c + 2, sb + SM_B((c + 2) % 3), tid);
            asm volatile("cp.async.commit_group;");
        }

        float acc[4][4][4];
#pragma unroll
        for (int mf = 0; mf < 4; mf++)
#pragma unroll
            for (int nf = 0; nf < 4; nf++)
#pragma unroll
                for (int v = 0; v < 4; v++) acc[mf][nf][v] = 0.0f;

#pragma unroll
        for (int kk = 0; kk < 4; kk++) {
            uint32_t b[4][2], a[4][4];
#pragma unroll
            for (int nf = 0; nf < 4; nf++)
                ldm_x2(b[nf], bbase + Bofs + (uint32_t)nf * (8 * BRS) + (uint32_t)kk * 32);
#pragma unroll
            for (int mf = 0; mf < 4; mf++)
                ldm_x4(a[mf], Abase + (uint32_t)mf * (16 * ARS) + (uint32_t)kk * 32);
#pragma unroll
            for (int mf = 0; mf < 4; mf++)
#pragma unroll
                for (int nf = 0; nf < 4; nf++)
                    mma16816(acc[mf][nf], a[mf], b[nf]);
        }

        // epilogue: s = acc - 0.5*b2, per-row top-2
#pragma unroll
        for (int nf = 0; nf < 4; nf++) {
            const int ng = c * NT + wn * 32 + nf * 8 + (lane & 3) * 2;
            const float2 bv = *(const float2*)&g_b2[ng];
#pragma unroll
            for (int mf = 0; mf < 4; mf++) {
                float s0 = fmaf(-0.5f, bv.x, acc[mf][nf][0]);
                float s1 = fmaf(-0.5f, bv.y, acc[mf][nf][1]);
                float s2 = fmaf(-0.5f, bv.x, acc[mf][nf][2]);
                float s3 = fmaf(-0.5f, bv.y, acc[mf][nf][3]);
                const int r0 = mf * 2, r1 = mf * 2 + 1;
                if (s0 > m1[r0]) { m2[r0] = m1[r0]; m1[r0] = s0; k1[r0] = ng; }
                else if (s0 > m2[r0]) m2[r0] = s0;
                if (s1 > m1[r0]) { m2[r0] = m1[r0]; m1[r0] = s1; k1[r0] = ng + 1; }
                else if (s1 > m2[r0]) m2[r0] = s1;
                if (s2 > m1[r1]) { m2[r1] = m1[r1]; m1[r1] = s2; k1[r1] = ng; }
                else if (s2 > m2[r1]) m2[r1] = s2;
                if (s3 > m1[r1]) { m2[r1] = m1[r1]; m1[r1] = s3; k1[r1] = ng + 1; }
                else if (s3 > m2[r1]) m2[r1] = s3;
            }
        }
    }

    // merge across the 4 quad lanes (same rows, different cols)
#pragma unroll
    for (int off = 1; off <= 2; off <<= 1) {
#pragma unroll
        for (int i = 0; i < 8; i++) {
            float om1 = __shfl_xor_sync(0xFFFFFFFFu, m1[i], off);
            float om2 = __shfl_xor_sync(0xFFFFFFFFu, m2[i], off);
            int   ok  = __shfl_xor_sync(0xFFFFFFFFu, k1[i], off);
            if (om1 > m1[i]) { m2[i] = fmaxf(m1[i], om2); m1[i] = om1; k1[i] = ok; }
            else             { m2[i] = fmaxf(m2[i], om1); }
        }
    }

    __syncthreads();   // smem reuse for cross-warp reduction
    float* RM1 = (float*)smem;                 // [256][4]
    float* RM2 = (float*)(smem + 4096);
    int*   RK  = (int*)(smem + 8192);
    if ((lane & 3) == 0) {
#pragma unroll
        for (int mf = 0; mf < 4; mf++)
#pragma unroll
            for (int h = 0; h < 2; h++) {
                int ri = mf * 2 + h;
                int rl = wm * 64 + mf * 16 + h * 8 + (lane >> 2);
                RM1[rl * 4 + wn] = m1[ri];
                RM2[rl * 4 + wn] = m2[ri];
                RK [rl * 4 + wn] = k1[ri];
            }
    }
    __syncthreads();
    if (tid < M_CTA) {
        float f1 = RM1[tid * 4], f2 = RM2[tid * 4]; int fk = RK[tid * 4];
#pragma unroll
        for (int w = 1; w < 4; w++) {
            float o1 = RM1[tid * 4 + w], o2 = RM2[tid * 4 + w]; int ok = RK[tid * 4 + w];
            if (o1 > f1) { f2 = fmaxf(f1, o2); f1 = o1; fk = ok; }
            else         { f2 = fmaxf(f2, o1); }
        }
        int grow = cta * M_CTA + tid;
        g_idx[grow] = fk;
        if (f1 - f2 < EPS_GAP) { int p = atomicAdd(&g_nflag, 1); g_flagrows[p] = grow; }
    }
}

// ---------------------------------------------------------------------------
// Kernel 4: exact a2 (XLA shfl tree) for flagged rows — warp per row
// ---------------------------------------------------------------------------
__global__ void vq_a2(const float* __restrict__ z) {
    int nf = g_nflag;
    int gw = (blockIdx.x * blockDim.x + threadIdx.x) >> 5;
    int lane = threadIdx.x & 31;
    int nwarps = (gridDim.x * blockDim.x) >> 5;
    for (int fi = gw; fi < nf; fi += nwarps) {
        int row = g_flagrows[fi];
        const float* zp = z + (size_t)(row >> 12) * (D_DIM * HW) + (row & 4095);
        float v1 = zp[(size_t)lane * HW], v2 = zp[(size_t)(lane + 32) * HW];
        float t = __fadd_rn(__fmul_rn(v1, v1), __fmul_rn(v2, v2));
#pragma unroll
        for (int off = 16; off >= 1; off >>= 1)
            t = __fadd_rn(t, __shfl_down_sync(0xFFFFFFFFu, t, off));
        if (lane == 0) g_a2f[fi] = t;
    }
}

// ---------------------------------------------------------------------------
// Kernel 5: parallel fallback — grid (64 tiles, 16 row-groups), bit-exact dist
// ---------------------------------------------------------------------------
__global__ __launch_bounds__(128)
void vq_fb_part(const float* __restrict__ z, const float* __restrict__ emb) {
    __shared__ float ec[128][68];
    __shared__ float zrow[64];
    __shared__ float b2c[128];
    __shared__ float wv[4];
    __shared__ int   wk[4];
    const int tid = threadIdx.x, t = blockIdx.x, grp = blockIdx.y;
    const int nf = g_nflag;
    if (grp >= nf) return;

    {
        const float4* g = (const float4*)(emb + (size_t)(t * 128 + tid) * D_DIM);
        float4* d = (float4*)&ec[tid][0];
#pragma unroll
        for (int i = 0; i < 16; i++) d[i] = g[i];
        b2c[tid] = g_b2[t * 128 + tid];
    }
    __syncthreads();

    for (int fi = grp; fi < nf; fi += 16) {
        if (tid < 64) {
            int row = g_flagrows[fi];
            zrow[tid] = z[(size_t)(row >> 12) * (D_DIM * HW) + (size_t)tid * HW + (row & 4095)];
        }
        __syncthreads();
        float acc = 0.0f;
        const float4* zb = (const float4*)&zrow[0];
        const float4* eb = (const float4*)&ec[tid][0];
#pragma unroll
        for (int i = 0; i < 16; i++) {
            float4 zv = zb[i], ev = eb[i];
            acc = fmaf(zv.x, ev.x, acc); acc = fmaf(zv.y, ev.y, acc);
            acc = fmaf(zv.z, ev.z, acc); acc = fmaf(zv.w, ev.w, acc);
        }
        float dist = __fadd_rn(__fsub_rn(g_a2f[fi], __fmul_rn(2.0f, acc)), b2c[tid]);
        int   kidx = t * 128 + tid;
#pragma unroll
        for (int off = 16; off >= 1; off >>= 1) {
            float ov = __shfl_down_sync(0xFFFFFFFFu, dist, off);
            int   ok = __shfl_down_sync(0xFFFFFFFFu, kidx, off);
            if (ov < dist || (ov == dist && ok < kidx)) { dist = ov; kidx = ok; }
        }
        if ((tid & 31) == 0) { wv[tid >> 5] = dist; wk[tid >> 5] = kidx; }
        __syncthreads();
        if (tid == 0) {
            float bv = wv[0]; int bk = wk[0];
#pragma unroll
            for (int w = 1; w < 4; w++)
                if (wv[w] < bv || (wv[w] == bv && wk[w] < bk)) { bv = wv[w]; bk = wk[w]; }
            g_pval[(size_t)fi * 64 + t] = bv;
            g_pidx[(size_t)fi * 64 + t] = bk;
        }
        __syncthreads();
    }
}

// ---------------------------------------------------------------------------
// Kernel 6: fallback reduce — warp per flagged row over 64 tile results
// ---------------------------------------------------------------------------
__global__ void vq_fb_red() {
    int nf = g_nflag;
    int gw = (blockIdx.x * blockDim.x + threadIdx.x) >> 5;
    int lane = threadIdx.x & 31;
    int nwarps = (gridDim.x * blockDim.x) >> 5;
    for (int fi = gw; fi < nf; fi += nwarps) {
        float v1 = g_pval[(size_t)fi * 64 + lane];
        int   k1 = g_pidx[(size_t)fi * 64 + lane];
        float v2 = g_pval[(size_t)fi * 64 + lane + 32];
        int   k2 = g_pidx[(size_t)fi * 64 + lane + 32];
        if (v2 < v1 || (v2 == v1 && k2 < k1)) { v1 = v2; k1 = k2; }
#pragma unroll
        for (int off = 16; off >= 1; off >>= 1) {
            float ov = __shfl_down_sync(0xFFFFFFFFu, v1, off);
            int   ok = __shfl_down_sync(0xFFFFFFFFu, k1, off);
            if (ov < v1 || (ov == v1 && ok < k1)) { v1 = ov; k1 = ok; }
        }
        if (lane == 0) g_idx[g_flagrows[fi]] = k1;
    }
}

// ---------------------------------------------------------------------------
// Kernel 7: gather + STE z_q + indices + counts + loss
// ---------------------------------------------------------------------------
__global__ __launch_bounds__(256)
void vq_final(const float* __restrict__ z, const float* __restrict__ emb,
              float* __restrict__ out, int out_size) {
    const int row = blockIdx.x * 256 + threadIdx.x;
    const int b = row >> 12, hw = row & 4095;
    const int bidx = g_idx[row];
    const float* zp = z + (size_t)b * (D_DIM * HW) + hw;
    const float* eb = emb + (size_t)bidx * D_DIM;
    float* zq = out + (size_t)b * (D_DIM * HW) + hw;
    const bool wz = (out_size >= NZ);
    float ssq = 0.0f;
#pragma unroll
    for (int d = 0; d < D_DIM; d++) {
        float zv = zp[(size_t)d * HW], ev = eb[d];
        float df = __fsub_rn(zv, ev);
        ssq = fmaf(df, df, ssq);
        if (wz) zq[(size_t)d * HW] = __fadd_rn(zv, __fsub_rn(ev, zv));
    }
    if (out_size >= NZ + NI) out[NZ + row] = (float)bidx;
    atomicAdd(&g_counts[bidx], 1);
#pragma unroll
    for (int o = 16; o > 0; o >>= 1) ssq += __shfl_down_sync(0xFFFFFFFFu, ssq, o);
    if ((threadIdx.x & 31) == 0) atomicAdd(&g_loss, ssq);
}

// ---------------------------------------------------------------------------
// Kernel 8: scalars
// ---------------------------------------------------------------------------
__global__ void vq_finalize(float* __restrict__ out, int out_size) {
    __shared__ float sH[256];
    __shared__ int   sU[256];
    const int tid = threadIdx.x;
    float H = 0.0f; int used = 0;
    for (int k = tid; k < K_CODES; k += 256) {
        float c = (float)g_counts[k];
        if (c > 0.0f) used++;
        float avg = c * (1.0f / (float)N_ROWS);
        H = fmaf(avg, logf(avg + 1e-10f), H);
    }
    sH[tid] = H; sU[tid] = used;
    __syncthreads();
    for (int s = 128; s > 0; s >>= 1) {
        if (tid < s) { sH[tid] += sH[tid + s]; sU[tid] += sU[tid + s]; }
        __syncthreads();
    }
    if (tid == 0 && out_size >= NZ + NI + 3) {
        out[NZ + NI + 0] = BETA * g_loss / (float)(N_ROWS * D_DIM);
        out[NZ + NI + 1] = expf(-sH[0]);
        out[NZ + NI + 2] = (float)sU[0] / (float)K_CODES;
    }
}

// ---------------------------------------------------------------------------
extern "C" void kernel_launch(void* const* d_in, const int* in_sizes, int n_in,
                              void* d_out, int out_size) {
    const float* z   = (const float*)d_in[0];
    const float* emb = (const float*)d_in[1];
    float* out = (float*)d_out;

    cudaFuncSetAttribute(vq_gemm, cudaFuncAttributeMaxDynamicSharedMemorySize, SM_TOT);

    vq_prep<<<(K_CODES * 32) / 256, 256>>>(emb);
    vq_prep_e<<<K_CODES / 256, 256>>>(emb);
    vq_gemm<<<CTAS, NTH, SM_TOT>>>(z);
    vq_a2<<<128, 256>>>(z);
    vq_fb_part<<<dim3(64, 16), 128>>>(z, emb);
    vq_fb_red<<<64, 256>>>();
    vq_final<<<N_ROWS / 256, 256>>>(z, emb, out, out_size);
    vq_finalize<<<1, 256>>>(out, out_size);
}

// round 9
// speedup vs baseline: 4.4708x; 1.1376x over previous
#include <cuda_runtime.h>
#include <cuda_fp16.h>
#include <math.h>
#include <stdint.h>

// VanillaVQ: z_e (8,64,64,64) fp32, embedding (8192,64) fp32.
// Outputs (concat fp32): z_q | indices | commit_loss | perplexity | usage.

#define K_CODES 8192
#define D_DIM   64
#define N_ROWS  32768
#define HW      4096
#define BETA    0.25f
#define NZ (N_ROWS * D_DIM)
#define NI N_ROWS
#define EPS_GAP 5e-4f

// GEMM config: S = fp16(z).fp16(e) (KD=64, certified by gap test)
#define M_CTA  128
#define CTAS   256
#define NTH    256          // 8 warps: 2(M) x 4(N)
#define NT     128          // codes per chunk
#define NCH    64
#define ARS    144          // row strides (16 mod 128 -> conflict-free ldmatrix)
#define BRS    144
#define SM_A   0            // 128*144 = 18432
#define SM_B(i) (18432u + (uint32_t)(i) * 18432u)   // 3 bufs
#define SM_TOT 73728

// ---------------- device scratch ----------------
__device__ float g_b2[K_CODES];
__device__ int   g_counts[K_CODES];
__device__ float g_loss;
__device__ int   g_nflag;
__device__ int   g_idx[N_ROWS];
__device__ int   g_flagrows[N_ROWS];
__device__ float g_a2f[N_ROWS];
__device__ float g_pval[N_ROWS * 64];
__device__ int   g_pidx[N_ROWS * 64];
__device__ __align__(128) uint32_t g_E[K_CODES * 32];   // 1MB fp16 image of emb

// ---------------- helpers ----------------
__device__ __forceinline__ uint32_t smem_u32(const void* p) {
    uint32_t a;
    asm("{ .reg .u64 t; cvta.to.shared.u64 t, %1; cvt.u32.u64 %0, t; }" : "=r"(a) : "l"(p));
    return a;
}
__device__ __forceinline__ uint32_t packh(float a, float b) {
    __half2 h = __floats2half2_rn(a, b);
    return *reinterpret_cast<uint32_t*>(&h);
}
__device__ __forceinline__ void ldm_x4(uint32_t* r, uint32_t addr) {
    asm volatile("ldmatrix.sync.aligned.m8n8.x4.shared.b16 {%0,%1,%2,%3}, [%4];"
                 : "=r"(r[0]), "=r"(r[1]), "=r"(r[2]), "=r"(r[3]) : "r"(addr));
}
__device__ __forceinline__ void ldm_x2(uint32_t* r, uint32_t addr) {
    asm volatile("ldmatrix.sync.aligned.m8n8.x2.shared.b16 {%0,%1}, [%2];"
                 : "=r"(r[0]), "=r"(r[1]) : "r"(addr));
}
__device__ __forceinline__ void mma16816(float* c, const uint32_t* a, const uint32_t* b) {
    asm volatile(
        "mma.sync.aligned.m16n8k16.row.col.f32.f16.f16.f32 "
        "{%0,%1,%2,%3}, {%4,%5,%6,%7}, {%8,%9}, {%0,%1,%2,%3};"
        : "+f"(c[0]), "+f"(c[1]), "+f"(c[2]), "+f"(c[3])
        : "r"(a[0]), "r"(a[1]), "r"(a[2]), "r"(a[3]), "r"(b[0]), "r"(b[1]));
}
__device__ __forceinline__ void cp16(uint32_t dst, const void* src) {
    uint64_t gs; asm("cvta.to.global.u64 %0, %1;" : "=l"(gs) : "l"(src));
    asm volatile("cp.async.cg.shared.global [%0], [%1], 16;" :: "r"(dst), "l"(gs));
}

// ---------------------------------------------------------------------------
// Kernel 1: b2 in XLA warp-tree order (warp per code)
// ---------------------------------------------------------------------------
__global__ void vq_prep_b2(const float* __restrict__ emb) {
    int gtid = blockIdx.x * blockDim.x + threadIdx.x;
    int k = gtid >> 5, lane = gtid & 31;
    if (k < K_CODES) {
        const float* e = emb + (size_t)k * D_DIM;
        float t = __fadd_rn(__fmul_rn(e[lane], e[lane]),
                            __fmul_rn(e[lane + 32], e[lane + 32]));
#pragma unroll
        for (int off = 16; off >= 1; off >>= 1)
            t = __fadd_rn(t, __shfl_down_sync(0xFFFFFFFFu, t, off));
        if (lane == 0) g_b2[k] = t;
    }
}

// ---------------------------------------------------------------------------
// Kernel 2: zero accumulators
// ---------------------------------------------------------------------------
__global__ void vq_prep_zero() {
    int k = blockIdx.x * blockDim.x + threadIdx.x;
    if (k < K_CODES) g_counts[k] = 0;
    if (k == 0) { g_loss = 0.0f; g_nflag = 0; }
}

// ---------------------------------------------------------------------------
// Kernel 3: fp16 image of emb (64 fp16 per code, 128B row)
// ---------------------------------------------------------------------------
__global__ void vq_prep_e(const float* __restrict__ emb) {
    int k = blockIdx.x * blockDim.x + threadIdx.x;
    if (k >= K_CODES) return;
    uint32_t* base = g_E + (size_t)k * 32;
    const float* e = emb + (size_t)k * D_DIM;
#pragma unroll 8
    for (int j = 0; j < 32; j++)
        base[j] = packh(e[2 * j], e[2 * j + 1]);
}

// ---------------------------------------------------------------------------
// Kernel 4: fp16 HMMA GEMM  S = z.e - 0.5*b2  + running top-2 + gap flag
// 256 CTAs x 256 threads (2M x 4N warps), warp tile 64x32, A hoisted to regs.
// ---------------------------------------------------------------------------
__device__ __forceinline__ void copy_chunk(int c, uint32_t dstbase, int tid) {
    const char* src = (const char*)g_E + (size_t)c * (NT * 128);
#pragma unroll
    for (int t = 0; t < 4; t++) {
        int idx = tid + t * NTH;                 // 0..1023
        int row = idx >> 3, seg = idx & 7;
        cp16(dstbase + (uint32_t)row * BRS + (uint32_t)seg * 16,
             src + (size_t)row * 128 + (size_t)seg * 16);
    }
}

__global__ __launch_bounds__(NTH, 1)
void vq_gemm(const float* __restrict__ z) {
    extern __shared__ __align__(128) char smem[];
    const uint32_t sb = smem_u32(smem);
    const int tid = threadIdx.x, cta = blockIdx.x;
    const int lane = tid & 31, warp = tid >> 5;
    const int wm = warp >> 2, wn = warp & 3;      // 2(M) x 4(N)

    // ---- build A tile: row r (<128): 64 fp16 of z ----
    if (tid < M_CTA) {
        int grow = cta * M_CTA + tid;
        const float* zp = z + (size_t)(grow >> 12) * (D_DIM * HW) + (grow & 4095);
        char* ar = smem + SM_A + (size_t)tid * ARS;
#pragma unroll 8
        for (int d = 0; d < 64; d += 2)
            *(uint32_t*)(ar + 2 * d) = packh(zp[(size_t)d * HW], zp[(size_t)(d + 1) * HW]);
    }
    __syncthreads();

    // ---- hoist A fragments to registers (chunk-invariant) ----
    const uint32_t Abase = sb + SM_A
        + (uint32_t)(wm * 64 + (lane & 7) + ((lane >> 3) & 1) * 8) * ARS
        + ((lane >> 4) & 1) * 16;
    uint32_t afr[4][4][4];
#pragma unroll
    for (int kk = 0; kk < 4; kk++)
#pragma unroll
        for (int mf = 0; mf < 4; mf++)
            ldm_x4(afr[kk][mf], Abase + (uint32_t)mf * (16 * ARS) + (uint32_t)kk * 32);

    copy_chunk(0, sb + SM_B(0), tid);
    asm volatile("cp.async.commit_group;");
    copy_chunk(1, sb + SM_B(1), tid);
    asm volatile("cp.async.commit_group;");

    const int bl = lane & 15;
    const uint32_t Bofs = (uint32_t)(wn * 32 + (bl & 7)) * BRS + ((bl >> 3) & 1) * 16;

    float m1[8], m2[8]; int k1[8];
#pragma unroll
    for (int i = 0; i < 8; i++) { m1[i] = -3.4e38f; m2[i] = -3.4e38f; k1[i] = 0; }

    for (int c = 0; c < NCH; c++) {
        const uint32_t bbase = sb + SM_B(c % 3);
        if (c == NCH - 1) asm volatile("cp.async.wait_group 0;");
        else              asm volatile("cp.async.wait_group 1;");
        __syncthreads();     // chunk c visible; buf (c+2)%3 free
        if (c + 2 < NCH) {
            copy_chunk(c + 2, sb + SM_B((c + 2) % 3), tid);
            asm volatile("cp.async.commit_group;");
        }

        float acc[4][4][4];
#pragma unroll
        for (int mf = 0; mf < 4; mf++)
#pragma unroll
            for (int nf = 0; nf < 4; nf++)
#pragma unroll
                for (int v = 0; v < 4; v++) acc[mf][nf][v] = 0.0f;

#pragma unroll
        for (int kk = 0; kk < 4; kk++) {
            uint32_t b[4][2];
#pragma unroll
            for (int nf = 0; nf < 4; nf++)
                ldm_x2(b[nf], bbase + Bofs + (uint32_t)nf * (8 * BRS) + (uint32_t)kk * 32);
#pragma unroll
            for (int mf = 0; mf < 4; mf++)
#pragma unroll
                for (int nf = 0; nf < 4; nf++)
                    mma16816(acc[mf][nf], afr[kk][mf], b[nf]);
        }

        // epilogue: s = acc - 0.5*b2, per-row top-2 (min/max form)
#pragma unroll
        for (int nf = 0; nf < 4; nf++) {
            const int ng = c * NT + wn * 32 + nf * 8 + (lane & 3) * 2;
            const float2 bv = *(const float2*)&g_b2[ng];
#pragma unroll
            for (int mf = 0; mf < 4; mf++) {
                const int r0 = mf * 2, r1 = mf * 2 + 1;
                float s;
                float o;
                s = fmaf(-0.5f, bv.x, acc[mf][nf][0]);
                o = m1[r0]; m2[r0] = fmaxf(m2[r0], fminf(s, o));
                if (s > o) { m1[r0] = s; k1[r0] = ng; }
                s = fmaf(-0.5f, bv.y, acc[mf][nf][1]);
                o = m1[r0]; m2[r0] = fmaxf(m2[r0], fminf(s, o));
                if (s > o) { m1[r0] = s; k1[r0] = ng + 1; }
                s = fmaf(-0.5f, bv.x, acc[mf][nf][2]);
                o = m1[r1]; m2[r1] = fmaxf(m2[r1], fminf(s, o));
                if (s > o) { m1[r1] = s; k1[r1] = ng; }
                s = fmaf(-0.5f, bv.y, acc[mf][nf][3]);
                o = m1[r1]; m2[r1] = fmaxf(m2[r1], fminf(s, o));
                if (s > o) { m1[r1] = s; k1[r1] = ng + 1; }
            }
        }
    }

    // merge across the 4 quad lanes (same rows, different cols)
#pragma unroll
    for (int off = 1; off <= 2; off <<= 1) {
#pragma unroll
        for (int i = 0; i < 8; i++) {
            float om1 = __shfl_xor_sync(0xFFFFFFFFu, m1[i], off);
            float om2 = __shfl_xor_sync(0xFFFFFFFFu, m2[i], off);
            int   ok  = __shfl_xor_sync(0xFFFFFFFFu, k1[i], off);
            if (om1 > m1[i]) { m2[i] = fmaxf(m1[i], om2); m1[i] = om1; k1[i] = ok; }
            else             { m2[i] = fmaxf(m2[i], om1); }
        }
    }

    __syncthreads();   // smem reuse for cross-warp reduction
    float* RM1 = (float*)smem;                 // [128][4]
    float* RM2 = (float*)(smem + 2048);
    int*   RK  = (int*)(smem + 4096);
    if ((lane & 3) == 0) {
#pragma unroll
        for (int mf = 0; mf < 4; mf++)
#pragma unroll
            for (int h = 0; h < 2; h++) {
                int ri = mf * 2 + h;
                int rl = wm * 64 + mf * 16 + h * 8 + (lane >> 2);
                RM1[rl * 4 + wn] = m1[ri];
                RM2[rl * 4 + wn] = m2[ri];
                RK [rl * 4 + wn] = k1[ri];
            }
    }
    __syncthreads();
    if (tid < M_CTA) {
        float f1 = RM1[tid * 4], f2 = RM2[tid * 4]; int fk = RK[tid * 4];
#pragma unroll
        for (int w = 1; w < 4; w++) {
            float o1 = RM1[tid * 4 + w], o2 = RM2[tid * 4 + w]; int ok = RK[tid * 4 + w];
            if (o1 > f1) { f2 = fmaxf(f1, o2); f1 = o1; fk = ok; }
            else         { f2 = fmaxf(f2, o1); }
        }
        int grow = cta * M_CTA + tid;
        g_idx[grow] = fk;
        if (f1 - f2 < EPS_GAP) { int p = atomicAdd(&g_nflag, 1); g_flagrows[p] = grow; }
    }
}

// ---------------------------------------------------------------------------
// Kernel 5: exact a2 (XLA shfl tree) for flagged rows — warp per row
// ---------------------------------------------------------------------------
__global__ void vq_a2(const float* __restrict__ z) {
    int nf = g_nflag;
    int gw = (blockIdx.x * blockDim.x + threadIdx.x) >> 5;
    int lane = threadIdx.x & 31;
    int nwarps = (gridDim.x * blockDim.x) >> 5;
    for (int fi = gw; fi < nf; fi += nwarps) {
        int row = g_flagrows[fi];
        const float* zp = z + (size_t)(row >> 12) * (D_DIM * HW) + (row & 4095);
        float v1 = zp[(size_t)lane * HW], v2 = zp[(size_t)(lane + 32) * HW];
        float t = __fadd_rn(__fmul_rn(v1, v1), __fmul_rn(v2, v2));
#pragma unroll
        for (int off = 16; off >= 1; off >>= 1)
            t = __fadd_rn(t, __shfl_down_sync(0xFFFFFFFFu, t, off));
        if (lane == 0) g_a2f[fi] = t;
    }
}

// ---------------------------------------------------------------------------
// Kernel 6: parallel fallback — grid (64 tiles, 16 row-groups), bit-exact dist
// ---------------------------------------------------------------------------
__global__ __launch_bounds__(128)
void vq_fb_part(const float* __restrict__ z, const float* __restrict__ emb) {
    __shared__ float ec[128][68];
    __shared__ float zrow[64];
    __shared__ float b2c[128];
    __shared__ float wv[4];
    __shared__ int   wk[4];
    const int tid = threadIdx.x, t = blockIdx.x, grp = blockIdx.y;
    const int nf = g_nflag;
    if (grp >= nf) return;

    {
        const float4* g = (const float4*)(emb + (size_t)(t * 128 + tid) * D_DIM);
        float4* d = (float4*)&ec[tid][0];
#pragma unroll
        for (int i = 0; i < 16; i++) d[i] = g[i];
        b2c[tid] = g_b2[t * 128 + tid];
    }
    __syncthreads();

    for (int fi = grp; fi < nf; fi += 16) {
        if (tid < 64) {
            int row = g_flagrows[fi];
            zrow[tid] = z[(size_t)(row >> 12) * (D_DIM * HW) + (size_t)tid * HW + (row & 4095)];
        }
        __syncthreads();
        float acc = 0.0f;
        const float4* zb = (const float4*)&zrow[0];
        const float4* eb = (const float4*)&ec[tid][0];
#pragma unroll
        for (int i = 0; i < 16; i++) {
            float4 zv = zb[i], ev = eb[i];
            acc = fmaf(zv.x, ev.x, acc); acc = fmaf(zv.y, ev.y, acc);
            acc = fmaf(zv.z, ev.z, acc); acc = fmaf(zv.w, ev.w, acc);
        }
        float dist = __fadd_rn(__fsub_rn(g_a2f[fi], __fmul_rn(2.0f, acc)), b2c[tid]);
        int   kidx = t * 128 + tid;
#pragma unroll
        for (int off = 16; off >= 1; off >>= 1) {
            float ov = __shfl_down_sync(0xFFFFFFFFu, dist, off);
            int   ok = __shfl_down_sync(0xFFFFFFFFu, kidx, off);
            if (ov < dist || (ov == dist && ok < kidx)) { dist = ov; kidx = ok; }
        }
        if ((tid & 31) == 0) { wv[tid >> 5] = dist; wk[tid >> 5] = kidx; }
        __syncthreads();
        if (tid == 0) {
            float bv = wv[0]; int bk = wk[0];
#pragma unroll
            for (int w = 1; w < 4; w++)
                if (wv[w] < bv || (wv[w] == bv && wk[w] < bk)) { bv = wv[w]; bk = wk[w]; }
            g_pval[(size_t)fi * 64 + t] = bv;
            g_pidx[(size_t)fi * 64 + t] = bk;
        }
        __syncthreads();
    }
}

// ---------------------------------------------------------------------------
// Kernel 7: fallback reduce — warp per flagged row over 64 tile results
// ---------------------------------------------------------------------------
__global__ void vq_fb_red() {
    int nf = g_nflag;
    int gw = (blockIdx.x * blockDim.x + threadIdx.x) >> 5;
    int lane = threadIdx.x & 31;
    int nwarps = (gridDim.x * blockDim.x) >> 5;
    for (int fi = gw; fi < nf; fi += nwarps) {
        float v1 = g_pval[(size_t)fi * 64 + lane];
        int   k1 = g_pidx[(size_t)fi * 64 + lane];
        float v2 = g_pval[(size_t)fi * 64 + lane + 32];
        int   k2 = g_pidx[(size_t)fi * 64 + lane + 32];
        if (v2 < v1 || (v2 == v1 && k2 < k1)) { v1 = v2; k1 = k2; }
#pragma unroll
        for (int off = 16; off >= 1; off >>= 1) {
            float ov = __shfl_down_sync(0xFFFFFFFFu, v1, off);
            int   ok = __shfl_down_sync(0xFFFFFFFFu, k1, off);
            if (ov < v1 || (ov == v1 && ok < k1)) { v1 = ov; k1 = ok; }
        }
        if (lane == 0) g_idx[g_flagrows[fi]] = k1;
    }
}

// ---------------------------------------------------------------------------
// Kernel 8: gather + STE z_q + indices + counts + loss
// ---------------------------------------------------------------------------
__global__ __launch_bounds__(256)
void vq_final(const float* __restrict__ z, const float* __restrict__ emb,
              float* __restrict__ out, int out_size) {
    const int row = blockIdx.x * 256 + threadIdx.x;
    const int b = row >> 12, hw = row & 4095;
    const int bidx = g_idx[row];
    const float* zp = z + (size_t)b * (D_DIM * HW) + hw;
    const float* eb = emb + (size_t)bidx * D_DIM;
    float* zq = out + (size_t)b * (D_DIM * HW) + hw;
    const bool wz = (out_size >= NZ);
    float ssq = 0.0f;
#pragma unroll
    for (int d = 0; d < D_DIM; d++) {
        float zv = zp[(size_t)d * HW], ev = eb[d];
        float df = __fsub_rn(zv, ev);
        ssq = fmaf(df, df, ssq);
        if (wz) zq[(size_t)d * HW] = __fadd_rn(zv, __fsub_rn(ev, zv));
    }
    if (out_size >= NZ + NI) out[NZ + row] = (float)bidx;
    atomicAdd(&g_counts[bidx], 1);
#pragma unroll
    for (int o = 16; o > 0; o >>= 1) ssq += __shfl_down_sync(0xFFFFFFFFu, ssq, o);
    if ((threadIdx.x & 31) == 0) atomicAdd(&g_loss, ssq);
}

// ---------------------------------------------------------------------------
// Kernel 9: scalars
// ---------------------------------------------------------------------------
__global__ void vq_finalize(float* __restrict__ out, int out_size) {
    __shared__ float sH[256];
    __shared__ int   sU[256];
    const int tid = threadIdx.x;
    float H = 0.0f; int used = 0;
    for (int k = tid; k < K_CODES; k += 256) {
        float c = (float)g_counts[k];
        if (c > 0.0f) used++;
        float avg = c * (1.0f / (float)N_ROWS);
        H = fmaf(avg, logf(avg + 1e-10f), H);
    }
    sH[tid] = H; sU[tid] = used;
    __syncthreads();
    for (int s = 128; s > 0; s >>= 1) {
        if (tid < s) { sH[tid] += sH[tid + s]; sU[tid] += sU[tid + s]; }
        __syncthreads();
    }
    if (tid == 0 && out_size >= NZ + NI + 3) {
        out[NZ + NI + 0] = BETA * g_loss / (float)(N_ROWS * D_DIM);
        out[NZ + NI + 1] = expf(-sH[0]);
        out[NZ + NI + 2] = (float)sU[0] / (float)K_CODES;
    }
}

// ---------------------------------------------------------------------------
extern "C" void kernel_launch(void* const* d_in, const int* in_sizes, int n_in,
                              void* d_out, int out_size) {
    const float* z   = (const float*)d_in[0];
    const float* emb = (const float*)d_in[1];
    float* out = (float*)d_out;

    cudaFuncSetAttribute(vq_gemm, cudaFuncAttributeMaxDynamicSharedMemorySize, SM_TOT);

    vq_prep_b2<<<(K_CODES * 32) / 256, 256>>>(emb);
    vq_prep_zero<<<K_CODES / 256, 256>>>();
    vq_prep_e<<<K_CODES / 256, 256>>>(emb);
    vq_gemm<<<CTAS, NTH, SM_TOT>>>(z);            // launch #4 (ncu capture slot)
    vq_a2<<<128, 256>>>(z);
    vq_fb_part<<<dim3(64, 16), 128>>>(z, emb);
    vq_fb_red<<<64, 256>>>();
    vq_final<<<N_ROWS / 256, 256>>>(z, emb, out, out_size);
    vq_finalize<<<1, 256>>>(out, out_size);
}